// round 2
// baseline (speedup 1.0000x reference)
#include <cuda_runtime.h>
#include <math.h>

#define BATCH 8
#define SEQ   1024
#define DIM   768
#define NH    12
#define HD    64
#define ROWS  (BATCH*SEQ)   // 8192

// Scratch (no allocations allowed -> __device__ globals)
__device__ float g_xn[ROWS*DIM];   // layernorm output, row-major [row][c]
__device__ float g_q [ROWS*DIM];   // head layout [(b*NH+h)][t][d], pre-scaled by 1/8, pos added
__device__ float g_k [ROWS*DIM];   // head layout
__device__ float g_v [ROWS*DIM];   // head layout
__device__ float g_av[ROWS*DIM];   // attention output, head layout

// ---------------------------------------------------------------------------
// LayerNorm: one block per row (768 cols, 256 threads x 3)
// ---------------------------------------------------------------------------
__global__ void ln_kernel(const float* __restrict__ x,
                          const float* __restrict__ gamma,
                          const float* __restrict__ beta) {
    int row = blockIdx.x;
    const float* xr = x + (size_t)row * DIM;
    int t = threadIdx.x;
    float v0 = xr[t], v1 = xr[t+256], v2 = xr[t+512];
    float s  = v0+v1+v2;
    float sq = v0*v0 + v1*v1 + v2*v2;
    __shared__ float red[2][8];
    #pragma unroll
    for (int o=16;o>0;o>>=1){
        s  += __shfl_xor_sync(0xffffffffu, s,  o);
        sq += __shfl_xor_sync(0xffffffffu, sq, o);
    }
    int wid = t>>5, lid = t&31;
    if (lid==0){ red[0][wid]=s; red[1][wid]=sq; }
    __syncthreads();
    if (t==0){
        float ss=0.f, ssq=0.f;
        #pragma unroll
        for (int i=0;i<8;i++){ ss+=red[0][i]; ssq+=red[1][i]; }
        float mu  = ss * (1.0f/DIM);
        float var = ssq * (1.0f/DIM) - mu*mu;
        red[0][0]=mu; red[1][0]=rsqrtf(var + 1e-5f);
    }
    __syncthreads();
    float mu = red[0][0], rstd = red[1][0];
    float* o = g_xn + (size_t)row * DIM;
    o[t]     = (v0-mu)*rstd*gamma[t]     + beta[t];
    o[t+256] = (v1-mu)*rstd*gamma[t+256] + beta[t+256];
    o[t+512] = (v2-mu)*rstd*gamma[t+512] + beta[t+512];
}

// ---------------------------------------------------------------------------
// QKV projection: C[8192x768] = xn @ W + b,  z in {0,1,2} picks Q/K/V.
// Tile: BM=64, BN=64, BK=16, 256 threads, 4x4 micro-tile.
// Epilogue writes head layout; Q additionally gets pos_embed and 1/8 scale.
// ---------------------------------------------------------------------------
__global__ void qkv_gemm(const float* __restrict__ Wq, const float* __restrict__ bq,
                         const float* __restrict__ Wk, const float* __restrict__ bk,
                         const float* __restrict__ Wv, const float* __restrict__ bv,
                         const float* __restrict__ pos) {
    int z = blockIdx.z;
    const float* W    = (z==0) ? Wq : ((z==1) ? Wk : Wv);
    const float* bias = (z==0) ? bq : ((z==1) ? bk : bv);
    float* out        = (z==0) ? g_q : ((z==1) ? g_k : g_v);

    __shared__ float As[16][65];   // [k][m], padded
    __shared__ float Bs[16][64];   // [k][n]

    int tid = threadIdx.x;
    int tx = tid & 15, ty = tid >> 4;
    int row0 = blockIdx.y * 64, col0 = blockIdx.x * 64;

    float acc[4][4] = {};

    int am = tid >> 2, ak = (tid & 3) * 4;   // A loader: 64 rows x 4 float4
    int bkk = tid >> 4, bj = (tid & 15) * 4; // B loader: 16 rows x 16 float4
    const float* Aptr = g_xn + (size_t)(row0 + am) * DIM + ak;
    const float* Bptr = W + (size_t)bkk * DIM + col0 + bj;

    for (int k0 = 0; k0 < DIM; k0 += 16) {
        float4 a4 = *(const float4*)(Aptr + k0);
        As[ak+0][am]=a4.x; As[ak+1][am]=a4.y; As[ak+2][am]=a4.z; As[ak+3][am]=a4.w;
        *(float4*)&Bs[bkk][bj] = *(const float4*)(Bptr + (size_t)k0 * DIM);
        __syncthreads();
        #pragma unroll
        for (int k = 0; k < 16; k++) {
            float4 b4 = *(const float4*)&Bs[k][tx*4];
            float b[4] = {b4.x, b4.y, b4.z, b4.w};
            float a[4];
            #pragma unroll
            for (int i=0;i<4;i++) a[i] = As[k][ty*4+i];
            #pragma unroll
            for (int i=0;i<4;i++)
                #pragma unroll
                for (int j=0;j<4;j++) acc[i][j] = fmaf(a[i], b[j], acc[i][j]);
        }
        __syncthreads();
    }

    #pragma unroll
    for (int i=0;i<4;i++){
        int r = row0 + ty*4 + i;
        int bb = r >> 10, tt = r & 1023;
        #pragma unroll
        for (int j=0;j<4;j++){
            int c = col0 + tx*4 + j;
            float v = acc[i][j] + bias[c];
            int h = c >> 6, d = c & 63;
            size_t oidx = ((size_t)((bb*NH + h)*SEQ + tt))*HD + d;
            if (z == 0) v = (v + pos[(size_t)r*DIM + c]) * 0.125f;  // inv_temp folded
            out[oidx] = v;
        }
    }
}

// ---------------------------------------------------------------------------
// Flash attention: block = one (b,h) + 64-query tile. Online softmax.
// Smem: Qs[d][r] pad65, Ks[d][c] pad65, Ps[c][r] pad65, Vs[c][d] stride64.
// ---------------------------------------------------------------------------
__global__ void attn_kernel() {
    extern __shared__ float smem_attn[];
    float* Qs = smem_attn;          // 64*65
    float* Ks = Qs + 64*65;         // 64*65
    float* Ps = Ks + 64*65;         // 64*65
    float* Vs = Ps + 64*65;         // 64*64

    int tid = threadIdx.x;
    int tx = tid & 15, ty = tid >> 4;
    int bh = blockIdx.y;
    int q0 = blockIdx.x * 64;

    const float* Qg = g_q + ((size_t)bh*SEQ + q0)*HD;
    const float* Kg = g_k + (size_t)bh*SEQ*HD;
    const float* Vg = g_v + (size_t)bh*SEQ*HD;

    // load Q tile transposed into Qs[d][r]
    #pragma unroll
    for (int l=0;l<4;l++){
        int idx = tid + l*256;          // float4 index, 1024 total
        int r = idx >> 4; int d = (idx & 15) * 4;
        float4 v = *(const float4*)(Qg + r*HD + d);
        Qs[(d+0)*65+r]=v.x; Qs[(d+1)*65+r]=v.y; Qs[(d+2)*65+r]=v.z; Qs[(d+3)*65+r]=v.w;
    }

    float m_run[4], l_run[4], o[4][4];
    #pragma unroll
    for (int i=0;i<4;i++){
        m_run[i] = -1e30f; l_run[i] = 0.f;
        #pragma unroll
        for (int j=0;j<4;j++) o[i][j] = 0.f;
    }

    for (int kt = 0; kt < 16; kt++) {
        __syncthreads();  // guard reuse of Ks/Vs/Ps (also orders Q load on 1st iter)
        #pragma unroll
        for (int l=0;l<4;l++){
            int idx = tid + l*256;
            int c = idx >> 4; int d = (idx & 15) * 4;
            float4 kv = *(const float4*)(Kg + (kt*64 + c)*HD + d);
            Ks[(d+0)*65+c]=kv.x; Ks[(d+1)*65+c]=kv.y; Ks[(d+2)*65+c]=kv.z; Ks[(d+3)*65+c]=kv.w;
            float4 vv = *(const float4*)(Vg + (kt*64 + c)*HD + d);
            *(float4*)&Vs[c*64 + d] = vv;
        }
        __syncthreads();

        // S = Q K^T for this tile (4x4 per thread)
        float s[4][4] = {};
        #pragma unroll 16
        for (int d=0; d<64; d++){
            float a[4], b[4];
            #pragma unroll
            for (int i=0;i<4;i++) a[i] = Qs[d*65 + ty*4 + i];
            #pragma unroll
            for (int j=0;j<4;j++) b[j] = Ks[d*65 + tx*4 + j];
            #pragma unroll
            for (int i=0;i<4;i++)
                #pragma unroll
                for (int j=0;j<4;j++) s[i][j] = fmaf(a[i], b[j], s[i][j]);
        }

        // online softmax per row (reduce across the 16 tx lanes of each half-warp)
        #pragma unroll
        for (int i=0;i<4;i++){
            float mx = fmaxf(fmaxf(s[i][0], s[i][1]), fmaxf(s[i][2], s[i][3]));
            #pragma unroll
            for (int off=8; off>0; off>>=1)
                mx = fmaxf(mx, __shfl_xor_sync(0xffffffffu, mx, off));
            float m_new = fmaxf(m_run[i], mx);
            float scale = __expf(m_run[i] - m_new);
            float rs = 0.f;
            #pragma unroll
            for (int j=0;j<4;j++){ float p = __expf(s[i][j] - m_new); s[i][j] = p; rs += p; }
            #pragma unroll
            for (int off=8; off>0; off>>=1)
                rs += __shfl_xor_sync(0xffffffffu, rs, off);
            l_run[i] = l_run[i]*scale + rs;
            m_run[i] = m_new;
            #pragma unroll
            for (int j=0;j<4;j++) o[i][j] *= scale;
        }

        // stage P transposed: Ps[c][r]
        #pragma unroll
        for (int i=0;i<4;i++)
            #pragma unroll
            for (int j=0;j<4;j++)
                Ps[(tx*4+j)*65 + ty*4+i] = s[i][j];
        __syncthreads();

        // O += P V
        #pragma unroll 16
        for (int c=0;c<64;c++){
            float a[4];
            #pragma unroll
            for (int i=0;i<4;i++) a[i] = Ps[c*65 + ty*4 + i];
            float4 b4 = *(const float4*)&Vs[c*64 + tx*4];
            float b[4] = {b4.x, b4.y, b4.z, b4.w};
            #pragma unroll
            for (int i=0;i<4;i++)
                #pragma unroll
                for (int j=0;j<4;j++) o[i][j] = fmaf(a[i], b[j], o[i][j]);
        }
    }

    float* Og = g_av + ((size_t)bh*SEQ + q0)*HD;
    #pragma unroll
    for (int i=0;i<4;i++){
        float inv = 1.0f / l_run[i];
        #pragma unroll
        for (int j=0;j<4;j++)
            Og[(ty*4+i)*HD + tx*4+j] = o[i][j]*inv;
    }
}

// ---------------------------------------------------------------------------
// Output projection: out = gather(g_av) @ Wo + bo + x   (residual)
// ---------------------------------------------------------------------------
__global__ void out_gemm(const float* __restrict__ Wo, const float* __restrict__ bo,
                         const float* __restrict__ x, float* __restrict__ out) {
    __shared__ float As[16][65];
    __shared__ float Bs[16][64];
    int tid = threadIdx.x;
    int tx = tid & 15, ty = tid >> 4;
    int row0 = blockIdx.y * 64, col0 = blockIdx.x * 64;
    float acc[4][4] = {};

    int am = tid >> 2, ak = (tid & 3) * 4;
    int bkk = tid >> 4, bj = (tid & 15) * 4;
    int r = row0 + am;
    int bb = r >> 10, tt = r & 1023;
    const float* Bptr = Wo + (size_t)bkk * DIM + col0 + bj;

    for (int k0 = 0; k0 < DIM; k0 += 16) {
        int h = k0 >> 6, d0 = k0 & 63;  // BK=16 never crosses a head boundary
        float4 a4 = *(const float4*)(g_av + ((size_t)((bb*NH + h)*SEQ + tt))*HD + d0 + ak);
        As[ak+0][am]=a4.x; As[ak+1][am]=a4.y; As[ak+2][am]=a4.z; As[ak+3][am]=a4.w;
        *(float4*)&Bs[bkk][bj] = *(const float4*)(Bptr + (size_t)k0 * DIM);
        __syncthreads();
        #pragma unroll
        for (int k = 0; k < 16; k++) {
            float4 b4 = *(const float4*)&Bs[k][tx*4];
            float b[4] = {b4.x, b4.y, b4.z, b4.w};
            float a[4];
            #pragma unroll
            for (int i=0;i<4;i++) a[i] = As[k][ty*4+i];
            #pragma unroll
            for (int i=0;i<4;i++)
                #pragma unroll
                for (int j=0;j<4;j++) acc[i][j] = fmaf(a[i], b[j], acc[i][j]);
        }
        __syncthreads();
    }

    #pragma unroll
    for (int i=0;i<4;i++){
        size_t rr = (size_t)(row0 + ty*4 + i) * DIM;
        #pragma unroll
        for (int j=0;j<4;j++){
            int c = col0 + tx*4 + j;
            out[rr + c] = acc[i][j] + bo[c] + x[rr + c];
        }
    }
}

// ---------------------------------------------------------------------------
extern "C" void kernel_launch(void* const* d_in, const int* in_sizes, int n_in,
                              void* d_out, int out_size) {
    const float* x     = (const float*)d_in[0];
    const float* pos   = (const float*)d_in[1];
    const float* gamma = (const float*)d_in[2];
    const float* beta  = (const float*)d_in[3];
    const float* Wq    = (const float*)d_in[4];
    const float* bq    = (const float*)d_in[5];
    const float* Wk    = (const float*)d_in[6];
    const float* bk    = (const float*)d_in[7];
    const float* Wv    = (const float*)d_in[8];
    const float* bv    = (const float*)d_in[9];
    const float* Wo    = (const float*)d_in[10];
    const float* bo    = (const float*)d_in[11];
    float* out = (float*)d_out;

    // One-time, idempotent attribute set (kept out of the per-call capture path).
    static bool s_attr_done = false;
    if (!s_attr_done) {
        cudaFuncSetAttribute(attn_kernel, cudaFuncAttributeMaxDynamicSharedMemorySize,
                             (int)((3*64*65 + 64*64) * sizeof(float)));
        s_attr_done = true;
    }

    ln_kernel<<<ROWS, 256>>>(x, gamma, beta);
    qkv_gemm<<<dim3(12, 128, 3), 256>>>(Wq, bq, Wk, bk, Wv, bv, pos);

    size_t smem = (size_t)(3*64*65 + 64*64) * sizeof(float);  // 66304 B
    attn_kernel<<<dim3(16, 96), 256, smem>>>();

    out_gemm<<<dim3(12, 128), 256>>>(Wo, bo, x, out);
}

// round 5
// speedup vs baseline: 1.5064x; 1.5064x over previous
#include <cuda_runtime.h>
#include <cuda_bf16.h>
#include <cstdint>
#include <math.h>

#define BATCH 8
#define SEQ   1024
#define DIM   768
#define NH    12
#define HD    64
#define ROWS  (BATCH*SEQ)   // 8192

// ---------------------------------------------------------------------------
// Scratch (__device__ globals; no allocations allowed)
// ---------------------------------------------------------------------------
__device__ __align__(16) __nv_bfloat16 g_xn_hi[ROWS*DIM];   // LN out split, row-major
__device__ __align__(16) __nv_bfloat16 g_xn_lo[ROWS*DIM];
__device__ __align__(16) __nv_bfloat16 g_wt_hi[4*DIM*DIM];  // W^T [n][k] split, z: q,k,v,o
__device__ __align__(16) __nv_bfloat16 g_wt_lo[4*DIM*DIM];
__device__ float g_q [ROWS*DIM];      // head layout [(b*NH+h)][t][d], 1/8-scaled, +pos
__device__ float g_k [ROWS*DIM];
__device__ float g_v [ROWS*DIM];
__device__ __align__(16) __nv_bfloat16 g_av_hi[ROWS*DIM];   // attn out, head layout, split
__device__ __align__(16) __nv_bfloat16 g_av_lo[ROWS*DIM];

// ---------------------------------------------------------------------------
// Base-ISA helpers (sm_80-era: ldmatrix / mma.sync / cp.async — OK on compute_100)
// ---------------------------------------------------------------------------
__device__ __forceinline__ uint32_t smem_u32(const void* p){
    uint32_t a;
    asm("{ .reg .u64 t; cvta.to.shared.u64 t, %1; cvt.u32.u64 %0, t; }" : "=r"(a) : "l"(p));
    return a;
}
#define CP_ASYNC16(dst, src) \
    asm volatile("cp.async.cg.shared.global [%0], [%1], 16;" :: "r"(dst), "l"(src))
#define CP_COMMIT() asm volatile("cp.async.commit_group;" ::: "memory")
#define CP_WAIT1()  asm volatile("cp.async.wait_group 1;" ::: "memory")
#define CP_WAIT0()  asm volatile("cp.async.wait_group 0;" ::: "memory")

__device__ __forceinline__ void ldm_x4(uint32_t& r0, uint32_t& r1, uint32_t& r2, uint32_t& r3,
                                       uint32_t addr){
    asm volatile("ldmatrix.sync.aligned.m8n8.x4.shared.b16 {%0,%1,%2,%3}, [%4];"
        : "=r"(r0), "=r"(r1), "=r"(r2), "=r"(r3) : "r"(addr));
}
__device__ __forceinline__ void mma_bf16(float* d, const uint32_t* a, const uint32_t* b){
    asm volatile("mma.sync.aligned.m16n8k16.row.col.f32.bf16.bf16.f32 "
        "{%0,%1,%2,%3}, {%4,%5,%6,%7}, {%8,%9}, {%0,%1,%2,%3};"
        : "+f"(d[0]), "+f"(d[1]), "+f"(d[2]), "+f"(d[3])
        : "r"(a[0]), "r"(a[1]), "r"(a[2]), "r"(a[3]), "r"(b[0]), "r"(b[1]));
}

// ---------------------------------------------------------------------------
// LayerNorm -> split bf16
// ---------------------------------------------------------------------------
__global__ void ln_kernel(const float* __restrict__ x,
                          const float* __restrict__ gamma,
                          const float* __restrict__ beta) {
    int row = blockIdx.x;
    const float* xr = x + (size_t)row * DIM;
    int t = threadIdx.x;
    float v0 = xr[t], v1 = xr[t+256], v2 = xr[t+512];
    float s  = v0+v1+v2;
    float sq = v0*v0 + v1*v1 + v2*v2;
    __shared__ float red[2][8];
    #pragma unroll
    for (int o=16;o>0;o>>=1){
        s  += __shfl_xor_sync(0xffffffffu, s,  o);
        sq += __shfl_xor_sync(0xffffffffu, sq, o);
    }
    int wid = t>>5, lid = t&31;
    if (lid==0){ red[0][wid]=s; red[1][wid]=sq; }
    __syncthreads();
    if (t==0){
        float ss=0.f, ssq=0.f;
        #pragma unroll
        for (int i=0;i<8;i++){ ss+=red[0][i]; ssq+=red[1][i]; }
        float mu  = ss * (1.0f/DIM);
        float var = ssq * (1.0f/DIM) - mu*mu;
        red[0][0]=mu; red[1][0]=rsqrtf(var + 1e-5f);
    }
    __syncthreads();
    float mu = red[0][0], rstd = red[1][0];
    size_t base = (size_t)row * DIM;
    #pragma unroll
    for (int l=0;l<3;l++){
        int c = t + l*256;
        float in = (l==0)?v0:((l==1)?v1:v2);
        float y = (in-mu)*rstd*gamma[c] + beta[c];
        __nv_bfloat16 h = __float2bfloat16(y);
        g_xn_hi[base+c] = h;
        g_xn_lo[base+c] = __float2bfloat16(y - __bfloat162float(h));
    }
}

// ---------------------------------------------------------------------------
// Weight transpose + split:  g_wt[z][n][k] = split(W_z[k][n])
// ---------------------------------------------------------------------------
__global__ void wconv(const float* __restrict__ Wq, const float* __restrict__ Wk,
                      const float* __restrict__ Wv, const float* __restrict__ Wo) {
    __shared__ float t[32][33];
    int z = blockIdx.z;
    const float* W = (z==0)?Wq : (z==1)?Wk : (z==2)?Wv : Wo;
    __nv_bfloat16* hi = g_wt_hi + (size_t)z*DIM*DIM;
    __nv_bfloat16* lo = g_wt_lo + (size_t)z*DIM*DIM;
    int k0 = blockIdx.y*32, n0 = blockIdx.x*32;
    int tx = threadIdx.x, ty = threadIdx.y;
    t[ty][tx] = W[(size_t)(k0+ty)*DIM + n0+tx];
    __syncthreads();
    float v = t[tx][ty];                 // = W[k0+tx][n0+ty]
    int n = n0+ty, k = k0+tx;
    __nv_bfloat16 h = __float2bfloat16(v);
    hi[(size_t)n*DIM + k] = h;
    lo[(size_t)n*DIM + k] = __float2bfloat16(v - __bfloat162float(h));
}

// ---------------------------------------------------------------------------
// mma.sync bf16 split-GEMM.  CTA tile M=128 x N=64, BK=32, double-buffered
// cp.async.  8 warps: warp_m = wid>>1 (4), warp_n = wid&1 (2); warp tile 32x32.
// Smem rows padded to 40 bf16 (80B) -> conflict-free ldmatrix.
// mode: blockIdx.z in {0,1,2} = Q/K/V (A = g_xn), base_mode==3 = out proj (A = g_av).
// ---------------------------------------------------------------------------
#define BKC     32
#define ASTR    40                       // bf16 elems per smem row (80 B)
#define OFF_AHI 0
#define OFF_ALO (128*ASTR*2)             // 10240
#define OFF_BHI (OFF_ALO + 128*ASTR*2)   // 20480
#define OFF_BLO (OFF_BHI + 64*ASTR*2)    // 25600
#define STAGE   (OFF_BLO + 64*ASTR*2)    // 30720
#define GEMM_SMEM (2*STAGE)              // 61440

__global__ void __launch_bounds__(256, 1) gemm_mma(
        int base_mode,
        const float* __restrict__ bq, const float* __restrict__ bk,
        const float* __restrict__ bv, const float* __restrict__ bo,
        const float* __restrict__ pos, const float* __restrict__ x,
        float* __restrict__ outp) {
    extern __shared__ char sm[];
    uint32_t sbase = smem_u32(sm);
    int tid = threadIdx.x, wid = tid>>5, lane = tid&31;
    int warp_m = wid>>1, warp_n = wid&1;
    int mode = (base_mode==3) ? 3 : (int)blockIdx.z;
    int col0 = blockIdx.x*64, row0 = blockIdx.y*128;

    const __nv_bfloat16* Bthi = g_wt_hi + (size_t)mode*DIM*DIM;
    const __nv_bfloat16* Btlo = g_wt_lo + (size_t)mode*DIM*DIM;
    const __nv_bfloat16* Ahi  = (mode<3) ? g_xn_hi : g_av_hi;
    const __nv_bfloat16* Alo  = (mode<3) ? g_xn_lo : g_av_lo;

    // ---- async loader for K-chunk kt into stage s ----
    auto load_chunk = [&](int kt, int s){
        uint32_t sb = sbase + s*STAGE;
        // A: 512 x 16B per matrix (128 rows x 4 segs); 2 per thread per matrix
        #pragma unroll
        for (int l=0;l<2;l++){
            int i = tid + l*256;                 // 0..511
            int r = i>>2, seg = i&3;
            int gk = kt*BKC + seg*8;
            size_t src;
            if (mode < 3) {
                src = (size_t)(row0+r)*DIM + gk;
            } else {
                int rr = row0+r; int bb = rr>>10, tt = rr&1023;
                src = (((size_t)(bb*NH + (gk>>6)))*SEQ + tt)*HD + (gk&63);
            }
            uint32_t dst = sb + OFF_AHI + (uint32_t)(r*(ASTR*2) + seg*16);
            CP_ASYNC16(dst,                         Ahi + src);
            CP_ASYNC16(dst + (OFF_ALO - OFF_AHI),   Alo + src);
        }
        // B: 256 x 16B per matrix (64 rows x 4 segs); 1 per thread per matrix
        {
            int r = tid>>2, seg = tid&3;
            size_t src = (size_t)(col0+r)*DIM + kt*BKC + seg*8;
            uint32_t dst = sb + OFF_BHI + (uint32_t)(r*(ASTR*2) + seg*16);
            CP_ASYNC16(dst,                         Bthi + src);
            CP_ASYNC16(dst + (OFF_BLO - OFF_BHI),   Btlo + src);
        }
        CP_COMMIT();
    };

    float acc[2][4][4];
    #pragma unroll
    for (int mt=0;mt<2;mt++)
        #pragma unroll
        for (int nt=0;nt<4;nt++)
            #pragma unroll
            for (int e=0;e<4;e++) acc[mt][nt][e]=0.f;

    const int NCHUNK = DIM / BKC;        // 24
    load_chunk(0, 0);

    int quad = lane>>3, r8 = lane&7;
    uint32_t rowA0 = (uint32_t)(warp_m*32 + (quad&1)*8 + r8);
    uint32_t rowB0 = (uint32_t)(warp_n*32 + (quad&1)*8 + r8);
    uint32_t colq  = (uint32_t)((quad>>1)*16);  // byte offset within k16 block

    for (int kt = 0; kt < NCHUNK; kt++) {
        int s = kt & 1;
        if (kt+1 < NCHUNK) { load_chunk(kt+1, (kt+1)&1); CP_WAIT1(); }
        else               { CP_WAIT0(); }
        __syncthreads();

        uint32_t sb = sbase + s*STAGE;
        #pragma unroll
        for (int k16 = 0; k16 < 2; k16++) {
            uint32_t kb = (uint32_t)(k16*32) + colq;   // byte col offset
            uint32_t ah[2][4], al[2][4];
            #pragma unroll
            for (int mt=0;mt<2;mt++){
                uint32_t ad = sb + OFF_AHI + (rowA0 + mt*16)*(ASTR*2) + kb;
                ldm_x4(ah[mt][0],ah[mt][1],ah[mt][2],ah[mt][3], ad);
                ldm_x4(al[mt][0],al[mt][1],al[mt][2],al[mt][3], ad + (OFF_ALO-OFF_AHI));
            }
            #pragma unroll
            for (int half=0; half<2; half++){
                uint32_t bd = sb + OFF_BHI + (rowB0 + half*16)*(ASTR*2) + kb;
                uint32_t h0,h1,h2,h3, l0,l1,l2,l3;
                ldm_x4(h0,h1,h2,h3, bd);
                ldm_x4(l0,l1,l2,l3, bd + (OFF_BLO-OFF_BHI));
                uint32_t bh0[2]={h0,h2}, bh1[2]={h1,h3};
                uint32_t bl0[2]={l0,l2}, bl1[2]={l1,l3};
                #pragma unroll
                for (int mt=0;mt<2;mt++){
                    mma_bf16(acc[mt][half*2+0], ah[mt], bh0);
                    mma_bf16(acc[mt][half*2+1], ah[mt], bh1);
                    mma_bf16(acc[mt][half*2+0], ah[mt], bl0);
                    mma_bf16(acc[mt][half*2+1], ah[mt], bl1);
                    mma_bf16(acc[mt][half*2+0], al[mt], bh0);
                    mma_bf16(acc[mt][half*2+1], al[mt], bh1);
                }
            }
        }
        __syncthreads();
    }

    // ---- epilogue ----
    int rA = lane>>2, cA = (lane&3)*2;
    #pragma unroll
    for (int mt=0;mt<2;mt++){
        #pragma unroll
        for (int nt=0;nt<4;nt++){
            int c = col0 + warp_n*32 + nt*8 + cA;
            #pragma unroll
            for (int half=0; half<2; half++){         // d0/d1 then d2/d3
                int m = row0 + warp_m*32 + mt*16 + rA + half*8;
                float v0 = acc[mt][nt][half*2+0];
                float v1 = acc[mt][nt][half*2+1];
                if (mode < 3) {
                    const float* bias = (mode==0)?bq : (mode==1)?bk : bv;
                    float* outg       = (mode==0)?g_q : (mode==1)?g_k : g_v;
                    int bb = m>>10, tt = m&1023, h = c>>6;
                    size_t ob = (((size_t)(bb*NH + h))*SEQ + tt)*HD + (c&63);
                    if (mode == 0) {
                        const float* pr = pos + (size_t)m*DIM + c;
                        outg[ob+0] = (v0 + bias[c]   + pr[0]) * 0.125f;
                        outg[ob+1] = (v1 + bias[c+1] + pr[1]) * 0.125f;
                    } else {
                        outg[ob+0] = v0 + bias[c];
                        outg[ob+1] = v1 + bias[c+1];
                    }
                } else {
                    size_t rb = (size_t)m*DIM + c;
                    outp[rb+0] = v0 + bo[c]   + x[rb+0];
                    outp[rb+1] = v1 + bo[c+1] + x[rb+1];
                }
            }
        }
    }
}

// ---------------------------------------------------------------------------
// Flash attention (fp32 SIMT): block = (b,h) x 64-query tile. Online softmax.
// Epilogue emits split-bf16 for the tensor-core output projection.
// ---------------------------------------------------------------------------
__global__ void attn_kernel() {
    extern __shared__ float smem_attn[];
    float* Qs = smem_attn;          // 64*65
    float* Ks = Qs + 64*65;
    float* Ps = Ks + 64*65;
    float* Vs = Ps + 64*65;         // 64*64

    int tid = threadIdx.x;
    int tx = tid & 15, ty = tid >> 4;
    int bh = blockIdx.y;
    int q0 = blockIdx.x * 64;

    const float* Qg = g_q + ((size_t)bh*SEQ + q0)*HD;
    const float* Kg = g_k + (size_t)bh*SEQ*HD;
    const float* Vg = g_v + (size_t)bh*SEQ*HD;

    #pragma unroll
    for (int l=0;l<4;l++){
        int idx = tid + l*256;
        int r = idx >> 4; int d = (idx & 15) * 4;
        float4 v = *(const float4*)(Qg + r*HD + d);
        Qs[(d+0)*65+r]=v.x; Qs[(d+1)*65+r]=v.y; Qs[(d+2)*65+r]=v.z; Qs[(d+3)*65+r]=v.w;
    }

    float m_run[4], l_run[4], o[4][4];
    #pragma unroll
    for (int i=0;i<4;i++){
        m_run[i] = -1e30f; l_run[i] = 0.f;
        #pragma unroll
        for (int j=0;j<4;j++) o[i][j] = 0.f;
    }

    for (int kt = 0; kt < 16; kt++) {
        __syncthreads();
        #pragma unroll
        for (int l=0;l<4;l++){
            int idx = tid + l*256;
            int c = idx >> 4; int d = (idx & 15) * 4;
            float4 kv = *(const float4*)(Kg + (kt*64 + c)*HD + d);
            Ks[(d+0)*65+c]=kv.x; Ks[(d+1)*65+c]=kv.y; Ks[(d+2)*65+c]=kv.z; Ks[(d+3)*65+c]=kv.w;
            float4 vv = *(const float4*)(Vg + (kt*64 + c)*HD + d);
            *(float4*)&Vs[c*64 + d] = vv;
        }
        __syncthreads();

        float s[4][4] = {};
        #pragma unroll 16
        for (int d=0; d<64; d++){
            float a[4], b[4];
            #pragma unroll
            for (int i=0;i<4;i++) a[i] = Qs[d*65 + ty*4 + i];
            #pragma unroll
            for (int j=0;j<4;j++) b[j] = Ks[d*65 + tx*4 + j];
            #pragma unroll
            for (int i=0;i<4;i++)
                #pragma unroll
                for (int j=0;j<4;j++) s[i][j] = fmaf(a[i], b[j], s[i][j]);
        }

        #pragma unroll
        for (int i=0;i<4;i++){
            float mx = fmaxf(fmaxf(s[i][0], s[i][1]), fmaxf(s[i][2], s[i][3]));
            #pragma unroll
            for (int off=8; off>0; off>>=1)
                mx = fmaxf(mx, __shfl_xor_sync(0xffffffffu, mx, off));
            float m_new = fmaxf(m_run[i], mx);
            float scale = __expf(m_run[i] - m_new);
            float rs = 0.f;
            #pragma unroll
            for (int j=0;j<4;j++){ float p = __expf(s[i][j] - m_new); s[i][j] = p; rs += p; }
            #pragma unroll
            for (int off=8; off>0; off>>=1)
                rs += __shfl_xor_sync(0xffffffffu, rs, off);
            l_run[i] = l_run[i]*scale + rs;
            m_run[i] = m_new;
            #pragma unroll
            for (int j=0;j<4;j++) o[i][j] *= scale;
        }

        #pragma unroll
        for (int i=0;i<4;i++)
            #pragma unroll
            for (int j=0;j<4;j++)
                Ps[(tx*4+j)*65 + ty*4+i] = s[i][j];
        __syncthreads();

        #pragma unroll 16
        for (int c=0;c<64;c++){
            float a[4];
            #pragma unroll
            for (int i=0;i<4;i++) a[i] = Ps[c*65 + ty*4 + i];
            float4 b4 = *(const float4*)&Vs[c*64 + tx*4];
            float b[4] = {b4.x, b4.y, b4.z, b4.w};
            #pragma unroll
            for (int i=0;i<4;i++)
                #pragma unroll
                for (int j=0;j<4;j++) o[i][j] = fmaf(a[i], b[j], o[i][j]);
        }
    }

    size_t obase = ((size_t)bh*SEQ + q0)*HD;
    #pragma unroll
    for (int i=0;i<4;i++){
        float inv = 1.0f / l_run[i];
        #pragma unroll
        for (int j=0;j<4;j++){
            float v = o[i][j]*inv;
            size_t idx = obase + (size_t)(ty*4+i)*HD + tx*4+j;
            __nv_bfloat16 h = __float2bfloat16(v);
            g_av_hi[idx] = h;
            g_av_lo[idx] = __float2bfloat16(v - __bfloat162float(h));
        }
    }
}

// ---------------------------------------------------------------------------
extern "C" void kernel_launch(void* const* d_in, const int* in_sizes, int n_in,
                              void* d_out, int out_size) {
    const float* x     = (const float*)d_in[0];
    const float* pos   = (const float*)d_in[1];
    const float* gamma = (const float*)d_in[2];
    const float* beta  = (const float*)d_in[3];
    const float* Wq    = (const float*)d_in[4];
    const float* bq    = (const float*)d_in[5];
    const float* Wk    = (const float*)d_in[6];
    const float* bk    = (const float*)d_in[7];
    const float* Wv    = (const float*)d_in[8];
    const float* bv    = (const float*)d_in[9];
    const float* Wo    = (const float*)d_in[10];
    const float* bo    = (const float*)d_in[11];
    float* out = (float*)d_out;

    static bool s_attr_done = false;
    if (!s_attr_done) {
        cudaFuncSetAttribute(attn_kernel, cudaFuncAttributeMaxDynamicSharedMemorySize,
                             (int)((3*64*65 + 64*64) * sizeof(float)));
        cudaFuncSetAttribute(gemm_mma, cudaFuncAttributeMaxDynamicSharedMemorySize,
                             GEMM_SMEM);
        s_attr_done = true;
    }

    ln_kernel<<<ROWS, 256>>>(x, gamma, beta);
    wconv<<<dim3(24, 24, 4), dim3(32, 32)>>>(Wq, Wk, Wv, Wo);

    // QKV projections on tensor cores (mode = blockIdx.z)
    gemm_mma<<<dim3(12, 64, 3), 256, GEMM_SMEM>>>(0, bq, bk, bv, bo, pos, x, out);

    size_t smem = (size_t)(3*64*65 + 64*64) * sizeof(float);  // 66304 B
    attn_kernel<<<dim3(16, 96), 256, smem>>>();

    // Output projection + bias + residual on tensor cores
    gemm_mma<<<dim3(12, 64, 1), 256, GEMM_SMEM>>>(3, bq, bk, bv, bo, pos, x, out);
}

// round 6
// speedup vs baseline: 2.5802x; 1.7128x over previous
#include <cuda_runtime.h>
#include <cuda_bf16.h>
#include <cstdint>
#include <math.h>

#define BATCH 8
#define SEQ   1024
#define DIM   768
#define NH    12
#define HD    64
#define ROWS  (BATCH*SEQ)   // 8192

// ---------------------------------------------------------------------------
// Scratch (__device__ globals; no allocations allowed)
// ---------------------------------------------------------------------------
__device__ __align__(16) __nv_bfloat16 g_xn_hi[ROWS*DIM];   // LN out split, row-major
__device__ __align__(16) __nv_bfloat16 g_xn_lo[ROWS*DIM];
__device__ __align__(16) __nv_bfloat16 g_wt_hi[4*DIM*DIM];  // W^T [n][k] split, z: q,k,v,o
__device__ __align__(16) __nv_bfloat16 g_wt_lo[4*DIM*DIM];
// Q/K/V split bf16, head layout [(b*NH+h)][t][d]; Q pre-scaled 1/8 with pos added
__device__ __align__(16) __nv_bfloat16 g_qh[ROWS*DIM];
__device__ __align__(16) __nv_bfloat16 g_ql[ROWS*DIM];
__device__ __align__(16) __nv_bfloat16 g_kh[ROWS*DIM];
__device__ __align__(16) __nv_bfloat16 g_kl[ROWS*DIM];
__device__ __align__(16) __nv_bfloat16 g_vh[ROWS*DIM];
__device__ __align__(16) __nv_bfloat16 g_vl[ROWS*DIM];
__device__ __align__(16) __nv_bfloat16 g_av_hi[ROWS*DIM];   // attn out, head layout, split
__device__ __align__(16) __nv_bfloat16 g_av_lo[ROWS*DIM];

// ---------------------------------------------------------------------------
// Base-ISA helpers (ldmatrix / mma.sync / cp.async — fine on compute_100)
// ---------------------------------------------------------------------------
__device__ __forceinline__ uint32_t smem_u32(const void* p){
    uint32_t a;
    asm("{ .reg .u64 t; cvta.to.shared.u64 t, %1; cvt.u32.u64 %0, t; }" : "=r"(a) : "l"(p));
    return a;
}
#define CP_ASYNC16(dst, src) \
    asm volatile("cp.async.cg.shared.global [%0], [%1], 16;" :: "r"(dst), "l"(src))
#define CP_COMMIT() asm volatile("cp.async.commit_group;" ::: "memory")
#define CP_WAIT1()  asm volatile("cp.async.wait_group 1;" ::: "memory")
#define CP_WAIT0()  asm volatile("cp.async.wait_group 0;" ::: "memory")

__device__ __forceinline__ void ldm_x4(uint32_t& r0, uint32_t& r1, uint32_t& r2, uint32_t& r3,
                                       uint32_t addr){
    asm volatile("ldmatrix.sync.aligned.m8n8.x4.shared.b16 {%0,%1,%2,%3}, [%4];"
        : "=r"(r0), "=r"(r1), "=r"(r2), "=r"(r3) : "r"(addr));
}
__device__ __forceinline__ void ldm_x4_t(uint32_t& r0, uint32_t& r1, uint32_t& r2, uint32_t& r3,
                                         uint32_t addr){
    asm volatile("ldmatrix.sync.aligned.m8n8.x4.trans.shared.b16 {%0,%1,%2,%3}, [%4];"
        : "=r"(r0), "=r"(r1), "=r"(r2), "=r"(r3) : "r"(addr));
}
__device__ __forceinline__ void mma_bf16(float* d, const uint32_t* a, const uint32_t* b){
    asm volatile("mma.sync.aligned.m16n8k16.row.col.f32.bf16.bf16.f32 "
        "{%0,%1,%2,%3}, {%4,%5,%6,%7}, {%8,%9}, {%0,%1,%2,%3};"
        : "+f"(d[0]), "+f"(d[1]), "+f"(d[2]), "+f"(d[3])
        : "r"(a[0]), "r"(a[1]), "r"(a[2]), "r"(a[3]), "r"(b[0]), "r"(b[1]));
}
__device__ __forceinline__ uint32_t pack_bf16x2(float lo, float hi){
    __nv_bfloat162 t = __floats2bfloat162_rn(lo, hi);   // .x = lo half
    return *(uint32_t*)&t;
}

// ---------------------------------------------------------------------------
// LayerNorm -> split bf16
// ---------------------------------------------------------------------------
__global__ void ln_kernel(const float* __restrict__ x,
                          const float* __restrict__ gamma,
                          const float* __restrict__ beta) {
    int row = blockIdx.x;
    const float* xr = x + (size_t)row * DIM;
    int t = threadIdx.x;
    float v0 = xr[t], v1 = xr[t+256], v2 = xr[t+512];
    float s  = v0+v1+v2;
    float sq = v0*v0 + v1*v1 + v2*v2;
    __shared__ float red[2][8];
    #pragma unroll
    for (int o=16;o>0;o>>=1){
        s  += __shfl_xor_sync(0xffffffffu, s,  o);
        sq += __shfl_xor_sync(0xffffffffu, sq, o);
    }
    int wid = t>>5, lid = t&31;
    if (lid==0){ red[0][wid]=s; red[1][wid]=sq; }
    __syncthreads();
    if (t==0){
        float ss=0.f, ssq=0.f;
        #pragma unroll
        for (int i=0;i<8;i++){ ss+=red[0][i]; ssq+=red[1][i]; }
        float mu  = ss * (1.0f/DIM);
        float var = ssq * (1.0f/DIM) - mu*mu;
        red[0][0]=mu; red[1][0]=rsqrtf(var + 1e-5f);
    }
    __syncthreads();
    float mu = red[0][0], rstd = red[1][0];
    size_t base = (size_t)row * DIM;
    #pragma unroll
    for (int l=0;l<3;l++){
        int c = t + l*256;
        float in = (l==0)?v0:((l==1)?v1:v2);
        float y = (in-mu)*rstd*gamma[c] + beta[c];
        __nv_bfloat16 h = __float2bfloat16(y);
        g_xn_hi[base+c] = h;
        g_xn_lo[base+c] = __float2bfloat16(y - __bfloat162float(h));
    }
}

// ---------------------------------------------------------------------------
// Weight transpose + split:  g_wt[z][n][k] = split(W_z[k][n])
// ---------------------------------------------------------------------------
__global__ void wconv(const float* __restrict__ Wq, const float* __restrict__ Wk,
                      const float* __restrict__ Wv, const float* __restrict__ Wo) {
    __shared__ float t[32][33];
    int z = blockIdx.z;
    const float* W = (z==0)?Wq : (z==1)?Wk : (z==2)?Wv : Wo;
    __nv_bfloat16* hi = g_wt_hi + (size_t)z*DIM*DIM;
    __nv_bfloat16* lo = g_wt_lo + (size_t)z*DIM*DIM;
    int k0 = blockIdx.y*32, n0 = blockIdx.x*32;
    int tx = threadIdx.x, ty = threadIdx.y;
    t[ty][tx] = W[(size_t)(k0+ty)*DIM + n0+tx];
    __syncthreads();
    float v = t[tx][ty];                 // = W[k0+tx][n0+ty]
    int n = n0+ty, k = k0+tx;
    __nv_bfloat16 h = __float2bfloat16(v);
    hi[(size_t)n*DIM + k] = h;
    lo[(size_t)n*DIM + k] = __float2bfloat16(v - __bfloat162float(h));
}

// ---------------------------------------------------------------------------
// mma.sync bf16 split-GEMM.  CTA tile M=128 x N=64, BK=32, double-buffered
// cp.async. 8 warps (4Mx2N), warp tile 32x32.
// modes 0,1,2 = Q/K/V (A = g_xn, out = split bf16 head layout); 3 = out proj.
// ---------------------------------------------------------------------------
#define BKC     32
#define ASTR    40
#define OFF_AHI 0
#define OFF_ALO (128*ASTR*2)
#define OFF_BHI (OFF_ALO + 128*ASTR*2)
#define OFF_BLO (OFF_BHI + 64*ASTR*2)
#define STAGE   (OFF_BLO + 64*ASTR*2)
#define GEMM_SMEM (2*STAGE)              // 61440

__global__ void __launch_bounds__(256, 1) gemm_mma(
        int base_mode,
        const float* __restrict__ bq, const float* __restrict__ bk,
        const float* __restrict__ bv, const float* __restrict__ bo,
        const float* __restrict__ pos, const float* __restrict__ x,
        float* __restrict__ outp) {
    extern __shared__ char sm[];
    uint32_t sbase = smem_u32(sm);
    int tid = threadIdx.x, wid = tid>>5, lane = tid&31;
    int warp_m = wid>>1, warp_n = wid&1;
    int mode = (base_mode==3) ? 3 : (int)blockIdx.z;
    int col0 = blockIdx.x*64, row0 = blockIdx.y*128;

    const __nv_bfloat16* Bthi = g_wt_hi + (size_t)mode*DIM*DIM;
    const __nv_bfloat16* Btlo = g_wt_lo + (size_t)mode*DIM*DIM;
    const __nv_bfloat16* Ahi  = (mode<3) ? g_xn_hi : g_av_hi;
    const __nv_bfloat16* Alo  = (mode<3) ? g_xn_lo : g_av_lo;

    auto load_chunk = [&](int kt, int s){
        uint32_t sb = sbase + s*STAGE;
        #pragma unroll
        for (int l=0;l<2;l++){
            int i = tid + l*256;
            int r = i>>2, seg = i&3;
            int gk = kt*BKC + seg*8;
            size_t src;
            if (mode < 3) {
                src = (size_t)(row0+r)*DIM + gk;
            } else {
                int rr = row0+r; int bb = rr>>10, tt = rr&1023;
                src = (((size_t)(bb*NH + (gk>>6)))*SEQ + tt)*HD + (gk&63);
            }
            uint32_t dst = sb + OFF_AHI + (uint32_t)(r*(ASTR*2) + seg*16);
            CP_ASYNC16(dst,                         Ahi + src);
            CP_ASYNC16(dst + (OFF_ALO - OFF_AHI),   Alo + src);
        }
        {
            int r = tid>>2, seg = tid&3;
            size_t src = (size_t)(col0+r)*DIM + kt*BKC + seg*8;
            uint32_t dst = sb + OFF_BHI + (uint32_t)(r*(ASTR*2) + seg*16);
            CP_ASYNC16(dst,                         Bthi + src);
            CP_ASYNC16(dst + (OFF_BLO - OFF_BHI),   Btlo + src);
        }
        CP_COMMIT();
    };

    float acc[2][4][4];
    #pragma unroll
    for (int mt=0;mt<2;mt++)
        #pragma unroll
        for (int nt=0;nt<4;nt++)
            #pragma unroll
            for (int e=0;e<4;e++) acc[mt][nt][e]=0.f;

    const int NCHUNK = DIM / BKC;        // 24
    load_chunk(0, 0);

    int quad = lane>>3, r8 = lane&7;
    uint32_t rowA0 = (uint32_t)(warp_m*32 + (quad&1)*8 + r8);
    uint32_t rowB0 = (uint32_t)(warp_n*32 + (quad&1)*8 + r8);
    uint32_t colq  = (uint32_t)((quad>>1)*16);

    for (int kt = 0; kt < NCHUNK; kt++) {
        int s = kt & 1;
        if (kt+1 < NCHUNK) { load_chunk(kt+1, (kt+1)&1); CP_WAIT1(); }
        else               { CP_WAIT0(); }
        __syncthreads();

        uint32_t sb = sbase + s*STAGE;
        #pragma unroll
        for (int k16 = 0; k16 < 2; k16++) {
            uint32_t kb = (uint32_t)(k16*32) + colq;
            uint32_t ah[2][4], al[2][4];
            #pragma unroll
            for (int mt=0;mt<2;mt++){
                uint32_t ad = sb + OFF_AHI + (rowA0 + mt*16)*(ASTR*2) + kb;
                ldm_x4(ah[mt][0],ah[mt][1],ah[mt][2],ah[mt][3], ad);
                ldm_x4(al[mt][0],al[mt][1],al[mt][2],al[mt][3], ad + (OFF_ALO-OFF_AHI));
            }
            #pragma unroll
            for (int half=0; half<2; half++){
                uint32_t bd = sb + OFF_BHI + (rowB0 + half*16)*(ASTR*2) + kb;
                uint32_t h0,h1,h2,h3, l0,l1,l2,l3;
                ldm_x4(h0,h1,h2,h3, bd);
                ldm_x4(l0,l1,l2,l3, bd + (OFF_BLO-OFF_BHI));
                uint32_t bh0[2]={h0,h2}, bh1[2]={h1,h3};
                uint32_t bl0[2]={l0,l2}, bl1[2]={l1,l3};
                #pragma unroll
                for (int mt=0;mt<2;mt++){
                    mma_bf16(acc[mt][half*2+0], ah[mt], bh0);
                    mma_bf16(acc[mt][half*2+1], ah[mt], bh1);
                    mma_bf16(acc[mt][half*2+0], ah[mt], bl0);
                    mma_bf16(acc[mt][half*2+1], ah[mt], bl1);
                    mma_bf16(acc[mt][half*2+0], al[mt], bh0);
                    mma_bf16(acc[mt][half*2+1], al[mt], bh1);
                }
            }
        }
        __syncthreads();
    }

    // ---- epilogue ----
    int rA = lane>>2, cA = (lane&3)*2;
    #pragma unroll
    for (int mt=0;mt<2;mt++){
        #pragma unroll
        for (int nt=0;nt<4;nt++){
            int c = col0 + warp_n*32 + nt*8 + cA;
            #pragma unroll
            for (int half=0; half<2; half++){
                int m = row0 + warp_m*32 + mt*16 + rA + half*8;
                float v0 = acc[mt][nt][half*2+0];
                float v1 = acc[mt][nt][half*2+1];
                if (mode < 3) {
                    const float* bias = (mode==0)?bq : (mode==1)?bk : bv;
                    __nv_bfloat16* oh = (mode==0)?g_qh : (mode==1)?g_kh : g_vh;
                    __nv_bfloat16* ol = (mode==0)?g_ql : (mode==1)?g_kl : g_vl;
                    int bb = m>>10, tt = m&1023, h = c>>6;
                    size_t ob = (((size_t)(bb*NH + h))*SEQ + tt)*HD + (c&63);
                    v0 += bias[c]; v1 += bias[c+1];
                    if (mode == 0) {
                        const float* pr = pos + (size_t)m*DIM + c;
                        v0 = (v0 + pr[0]) * 0.125f;
                        v1 = (v1 + pr[1]) * 0.125f;
                    }
                    __nv_bfloat16 h0 = __float2bfloat16(v0);
                    __nv_bfloat16 h1 = __float2bfloat16(v1);
                    oh[ob+0] = h0; ol[ob+0] = __float2bfloat16(v0 - __bfloat162float(h0));
                    oh[ob+1] = h1; ol[ob+1] = __float2bfloat16(v1 - __bfloat162float(h1));
                } else {
                    size_t rb = (size_t)m*DIM + c;
                    outp[rb+0] = v0 + bo[c]   + x[rb+0];
                    outp[rb+1] = v1 + bo[c+1] + x[rb+1];
                }
            }
        }
    }
}

// ---------------------------------------------------------------------------
// Tensor-core flash attention.
// Block: 128 queries x one (b,h); 8 warps x 16 rows. K-tiles of 64 keys,
// double-buffered cp.async. S and PV via mma.sync with 3-term bf16 split.
// P stays in registers (C-frag == A-frag layout identity).
// Smem rows: 64 dims * 2B + 16B pad = 144B (bank step 4 -> conflict-free).
// ---------------------------------------------------------------------------
#define ATR        144                    // bytes per smem row
#define AT_Q_HI    0
#define AT_Q_LO    (128*ATR)              // 18432
#define AT_STG     (2*128*ATR)            // 36864 : stage base
#define AT_STG_SZ  (4*64*ATR)             // 36864 : KHI,KLO,VHI,VLO
#define AT_K_HI    0
#define AT_K_LO    (64*ATR)
#define AT_V_HI    (2*64*ATR)
#define AT_V_LO    (3*64*ATR)
#define ATT_SMEM   (AT_STG + 2*AT_STG_SZ) // 110592

__global__ void __launch_bounds__(256, 1) attn_mma() {
    extern __shared__ char sm[];
    uint32_t sbase = smem_u32(sm);
    int tid = threadIdx.x, wid = tid>>5, lane = tid&31;
    int bh = blockIdx.y;
    int q0 = blockIdx.x * 128;
    int wq0 = wid * 16;

    size_t hbase = (size_t)bh*SEQ*HD;
    const __nv_bfloat16* Qh = g_qh + hbase + (size_t)q0*HD;
    const __nv_bfloat16* Ql = g_ql + hbase + (size_t)q0*HD;

    // ---- group 0: Q (both splits) + K/V stage 0 ----
    {
        #pragma unroll
        for (int l=0;l<8;l++){
            int i = tid + l*256;            // 0..2047
            int mat = i>>10;                // 0=hi 1=lo
            int r = (i&1023)>>3, seg = i&7;
            const __nv_bfloat16* src = (mat? Ql : Qh) + (size_t)r*HD + seg*8;
            uint32_t dst = sbase + (mat? AT_Q_LO : AT_Q_HI) + (uint32_t)(r*ATR + seg*16);
            CP_ASYNC16(dst, src);
        }
        #pragma unroll
        for (int l=0;l<8;l++){
            int i = tid + l*256;
            int mat = i>>9;                 // 0..3
            int r = (i&511)>>3, seg = i&7;
            const __nv_bfloat16* base = (mat==0)? g_kh : (mat==1)? g_kl : (mat==2)? g_vh : g_vl;
            const __nv_bfloat16* src = base + hbase + (size_t)r*HD + seg*8;
            uint32_t dst = sbase + AT_STG + (uint32_t)(mat*(64*ATR) + r*ATR + seg*16);
            CP_ASYNC16(dst, src);
        }
        CP_COMMIT();
    }

    uint32_t qh[4][4], ql[4][4];
    float oacc[8][4];
    #pragma unroll
    for (int f=0;f<8;f++)
        #pragma unroll
        for (int e=0;e<4;e++) oacc[f][e]=0.f;
    float m0 = -1e30f, m1 = -1e30f, l0 = 0.f, l1 = 0.f;

    int g = lane>>3, r8 = lane&7;

    const int NKT = SEQ/64;    // 16
    for (int kt = 0; kt < NKT; kt++) {
        int s = kt & 1;
        if (kt+1 < NKT) {
            uint32_t sb = sbase + AT_STG + ((kt+1)&1)*AT_STG_SZ;
            #pragma unroll
            for (int l=0;l<8;l++){
                int i = tid + l*256;
                int mat = i>>9;
                int r = (i&511)>>3, seg = i&7;
                const __nv_bfloat16* base = (mat==0)? g_kh : (mat==1)? g_kl : (mat==2)? g_vh : g_vl;
                const __nv_bfloat16* src = base + hbase + (size_t)((kt+1)*64 + r)*HD + seg*8;
                uint32_t dst = sb + (uint32_t)(mat*(64*ATR) + r*ATR + seg*16);
                CP_ASYNC16(dst, src);
            }
            CP_COMMIT();
            CP_WAIT1();
        } else {
            CP_WAIT0();
        }
        __syncthreads();

        if (kt == 0) {
            // preload Q fragments (A layout): g0 rows lo/d lo, g1 rows hi/d lo,
            // g2 rows lo/d hi, g3 rows hi/d hi
            uint32_t qrow = (uint32_t)(wq0 + ((g&1)?8:0) + r8);
            #pragma unroll
            for (int t=0;t<4;t++){
                uint32_t ad = sbase + qrow*ATR + (uint32_t)(32*t + ((g&2)?16:0));
                ldm_x4(qh[t][0],qh[t][1],qh[t][2],qh[t][3], ad + AT_Q_HI);
                ldm_x4(ql[t][0],ql[t][1],ql[t][2],ql[t][3], ad + AT_Q_LO);
            }
        }

        uint32_t stg = sbase + AT_STG + s*AT_STG_SZ;

        // ---- S = Q K^T (16q x 64 keys per warp), 3-term split ----
        float sv[8][4];
        #pragma unroll
        for (int f=0;f<8;f++)
            #pragma unroll
            for (int e=0;e<4;e++) sv[f][e]=0.f;

        // K frag addresses (B operand, non-trans): g0 keys-lo/d-lo, g1 keys-lo/d-hi,
        // g2 keys-hi/d-lo, g3 keys-hi/d-hi
        uint32_t krow_off = (uint32_t)(((g&2)?8:0) + r8);
        uint32_t kcol_b   = (uint32_t)((g&1)?16:0);
        #pragma unroll
        for (int j=0;j<4;j++){
            #pragma unroll
            for (int t=0;t<4;t++){
                uint32_t ad = stg + (uint32_t)((16*j)+krow_off)*ATR + (uint32_t)(32*t) + kcol_b;
                uint32_t b0,b1,b2,b3, c0,c1,c2,c3;
                ldm_x4(b0,b1,b2,b3, ad + AT_K_HI);
                ldm_x4(c0,c1,c2,c3, ad + AT_K_LO);
                uint32_t bh0[2]={b0,b1}, bh1[2]={b2,b3};
                uint32_t bl0[2]={c0,c1}, bl1[2]={c2,c3};
                mma_bf16(sv[2*j],   qh[t], bh0);
                mma_bf16(sv[2*j],   qh[t], bl0);
                mma_bf16(sv[2*j],   ql[t], bh0);
                mma_bf16(sv[2*j+1], qh[t], bh1);
                mma_bf16(sv[2*j+1], qh[t], bl1);
                mma_bf16(sv[2*j+1], ql[t], bh1);
            }
        }

        // ---- online softmax in fragments (rows: gID and gID+8) ----
        float mx0 = -1e30f, mx1 = -1e30f;
        #pragma unroll
        for (int f=0;f<8;f++){
            mx0 = fmaxf(mx0, fmaxf(sv[f][0], sv[f][1]));
            mx1 = fmaxf(mx1, fmaxf(sv[f][2], sv[f][3]));
        }
        #pragma unroll
        for (int off=1; off<4; off<<=1){
            mx0 = fmaxf(mx0, __shfl_xor_sync(0xffffffffu, mx0, off));
            mx1 = fmaxf(mx1, __shfl_xor_sync(0xffffffffu, mx1, off));
        }
        float mn0 = fmaxf(m0, mx0), mn1 = fmaxf(m1, mx1);
        float sc0 = __expf(m0 - mn0), sc1 = __expf(m1 - mn1);
        m0 = mn0; m1 = mn1;
        float sum0 = 0.f, sum1 = 0.f;
        #pragma unroll
        for (int f=0;f<8;f++){
            sv[f][0] = __expf(sv[f][0] - m0);
            sv[f][1] = __expf(sv[f][1] - m0);
            sv[f][2] = __expf(sv[f][2] - m1);
            sv[f][3] = __expf(sv[f][3] - m1);
            sum0 += sv[f][0] + sv[f][1];
            sum1 += sv[f][2] + sv[f][3];
        }
        #pragma unroll
        for (int off=1; off<4; off<<=1){
            sum0 += __shfl_xor_sync(0xffffffffu, sum0, off);
            sum1 += __shfl_xor_sync(0xffffffffu, sum1, off);
        }
        l0 = l0*sc0 + sum0;
        l1 = l1*sc1 + sum1;
        #pragma unroll
        for (int f=0;f<8;f++){
            oacc[f][0] *= sc0; oacc[f][1] *= sc0;
            oacc[f][2] *= sc1; oacc[f][3] *= sc1;
        }

        // ---- O += P V, P in registers (C-frag == A-frag), 3-term split ----
        // V frag addresses (trans): g0 keys-lo/d-lo, g1 keys-hi/d-lo,
        // g2 keys-lo/d-hi, g3 keys-hi/d-hi
        uint32_t vrow_off = (uint32_t)(((g&1)?8:0) + r8);
        uint32_t vcol_b   = (uint32_t)((g&2)?16:0);
        #pragma unroll
        for (int j=0;j<4;j++){
            uint32_t pah[4], pal[4];
            #pragma unroll
            for (int hf=0; hf<2; hf++){      // frag 2j (rows lo) pairs, 2j+1
                #pragma unroll
                for (int pp=0; pp<2; pp++){
                    float e0 = sv[2*j+hf][pp*2+0];
                    float e1 = sv[2*j+hf][pp*2+1];
                    __nv_bfloat16 b0 = __float2bfloat16(e0);
                    __nv_bfloat16 b1 = __float2bfloat16(e1);
                    pah[hf*2+pp] = pack_bf16x2(__bfloat162float(b0), __bfloat162float(b1)) ;
                    pal[hf*2+pp] = pack_bf16x2(e0 - __bfloat162float(b0),
                                               e1 - __bfloat162float(b1));
                }
            }
            // reorder: A-frag = {c01(2j), c23(2j), c01(2j+1), c23(2j+1)}
            uint32_t pa_h[4] = {pah[0], pah[1], pah[2], pah[3]};
            uint32_t pa_l[4] = {pal[0], pal[1], pal[2], pal[3]};
            #pragma unroll
            for (int gg=0; gg<4; gg++){
                uint32_t ad = stg + (uint32_t)((16*j)+vrow_off)*ATR + (uint32_t)(32*gg) + vcol_b;
                uint32_t v0,v1,v2,v3, w0,w1,w2,w3;
                ldm_x4_t(v0,v1,v2,v3, ad + AT_V_HI);
                ldm_x4_t(w0,w1,w2,w3, ad + AT_V_LO);
                uint32_t bh0[2]={v0,v1}, bh1[2]={v2,v3};
                uint32_t bl0[2]={w0,w1}, bl1[2]={w2,w3};
                mma_bf16(oacc[2*gg],   pa_h, bh0);
                mma_bf16(oacc[2*gg],   pa_h, bl0);
                mma_bf16(oacc[2*gg],   pa_l, bh0);
                mma_bf16(oacc[2*gg+1], pa_h, bh1);
                mma_bf16(oacc[2*gg+1], pa_h, bl1);
                mma_bf16(oacc[2*gg+1], pa_l, bh1);
            }
        }
        __syncthreads();
    }

    // ---- epilogue: normalize, split, store head-layout ----
    float inv0 = 1.0f / l0, inv1 = 1.0f / l1;
    int gID = lane>>2, c2 = (lane&3)*2;
    size_t ob0 = hbase + (size_t)(q0 + wq0 + gID)*HD;
    size_t ob1 = hbase + (size_t)(q0 + wq0 + gID + 8)*HD;
    #pragma unroll
    for (int f=0;f<8;f++){
        int d = f*8 + c2;
        float a0 = oacc[f][0]*inv0, a1 = oacc[f][1]*inv0;
        float b0 = oacc[f][2]*inv1, b1 = oacc[f][3]*inv1;
        __nv_bfloat16 h;
        h = __float2bfloat16(a0); g_av_hi[ob0+d]   = h; g_av_lo[ob0+d]   = __float2bfloat16(a0 - __bfloat162float(h));
        h = __float2bfloat16(a1); g_av_hi[ob0+d+1] = h; g_av_lo[ob0+d+1] = __float2bfloat16(a1 - __bfloat162float(h));
        h = __float2bfloat16(b0); g_av_hi[ob1+d]   = h; g_av_lo[ob1+d]   = __float2bfloat16(b0 - __bfloat162float(h));
        h = __float2bfloat16(b1); g_av_hi[ob1+d+1] = h; g_av_lo[ob1+d+1] = __float2bfloat16(b1 - __bfloat162float(h));
    }
}

// ---------------------------------------------------------------------------
extern "C" void kernel_launch(void* const* d_in, const int* in_sizes, int n_in,
                              void* d_out, int out_size) {
    const float* x     = (const float*)d_in[0];
    const float* pos   = (const float*)d_in[1];
    const float* gamma = (const float*)d_in[2];
    const float* beta  = (const float*)d_in[3];
    const float* Wq    = (const float*)d_in[4];
    const float* bq    = (const float*)d_in[5];
    const float* Wk    = (const float*)d_in[6];
    const float* bk    = (const float*)d_in[7];
    const float* Wv    = (const float*)d_in[8];
    const float* bv    = (const float*)d_in[9];
    const float* Wo    = (const float*)d_in[10];
    const float* bo    = (const float*)d_in[11];
    float* out = (float*)d_out;

    static bool s_attr_done = false;
    if (!s_attr_done) {
        cudaFuncSetAttribute(gemm_mma, cudaFuncAttributeMaxDynamicSharedMemorySize,
                             GEMM_SMEM);
        cudaFuncSetAttribute(attn_mma, cudaFuncAttributeMaxDynamicSharedMemorySize,
                             ATT_SMEM);
        s_attr_done = true;
    }

    ln_kernel<<<ROWS, 256>>>(x, gamma, beta);
    wconv<<<dim3(24, 24, 4), dim3(32, 32)>>>(Wq, Wk, Wv, Wo);

    gemm_mma<<<dim3(12, 64, 3), 256, GEMM_SMEM>>>(0, bq, bk, bv, bo, pos, x, out);

    attn_mma<<<dim3(SEQ/128, BATCH*NH), 256, ATT_SMEM>>>();

    gemm_mma<<<dim3(12, 64, 1), 256, GEMM_SMEM>>>(3, bq, bk, bv, bo, pos, x, out);
}

// round 8
// speedup vs baseline: 2.6333x; 1.0206x over previous
#include <cuda_runtime.h>
#include <cuda_bf16.h>
#include <cstdint>
#include <math.h>

#define BATCH 8
#define SEQ   1024
#define DIM   768
#define NH    12
#define HD    64
#define ROWS  (BATCH*SEQ)   // 8192

// ---------------------------------------------------------------------------
// Scratch (__device__ globals; no allocations allowed)
// ---------------------------------------------------------------------------
__device__ __align__(16) __nv_bfloat16 g_xn_hi[ROWS*DIM];   // LN out split, row-major
__device__ __align__(16) __nv_bfloat16 g_xn_lo[ROWS*DIM];
__device__ __align__(16) __nv_bfloat16 g_wt_hi[4*DIM*DIM];  // W^T [n][k] split, z: q,k,v,o
__device__ __align__(16) __nv_bfloat16 g_wt_lo[4*DIM*DIM];
// Q/K/V split bf16, head layout [(b*NH+h)][t][d]; Q pre-scaled 1/8 with pos added
__device__ __align__(16) __nv_bfloat16 g_qh[ROWS*DIM];
__device__ __align__(16) __nv_bfloat16 g_ql[ROWS*DIM];
__device__ __align__(16) __nv_bfloat16 g_kh[ROWS*DIM];
__device__ __align__(16) __nv_bfloat16 g_kl[ROWS*DIM];
__device__ __align__(16) __nv_bfloat16 g_vh[ROWS*DIM];
__device__ __align__(16) __nv_bfloat16 g_vl[ROWS*DIM];
__device__ __align__(16) __nv_bfloat16 g_av_hi[ROWS*DIM];   // attn out, head layout, split
__device__ __align__(16) __nv_bfloat16 g_av_lo[ROWS*DIM];

// ---------------------------------------------------------------------------
// Base-ISA helpers (ldmatrix / mma.sync / cp.async — fine on compute_100)
// ---------------------------------------------------------------------------
__device__ __forceinline__ uint32_t smem_u32(const void* p){
    uint32_t a;
    asm("{ .reg .u64 t; cvta.to.shared.u64 t, %1; cvt.u32.u64 %0, t; }" : "=r"(a) : "l"(p));
    return a;
}
#define CP_ASYNC16(dst, src) \
    asm volatile("cp.async.cg.shared.global [%0], [%1], 16;" :: "r"(dst), "l"(src))
#define CP_COMMIT() asm volatile("cp.async.commit_group;" ::: "memory")
#define CP_WAIT1()  asm volatile("cp.async.wait_group 1;" ::: "memory")
#define CP_WAIT0()  asm volatile("cp.async.wait_group 0;" ::: "memory")

__device__ __forceinline__ void ldm_x4(uint32_t& r0, uint32_t& r1, uint32_t& r2, uint32_t& r3,
                                       uint32_t addr){
    asm volatile("ldmatrix.sync.aligned.m8n8.x4.shared.b16 {%0,%1,%2,%3}, [%4];"
        : "=r"(r0), "=r"(r1), "=r"(r2), "=r"(r3) : "r"(addr));
}
__device__ __forceinline__ void ldm_x4_t(uint32_t& r0, uint32_t& r1, uint32_t& r2, uint32_t& r3,
                                         uint32_t addr){
    asm volatile("ldmatrix.sync.aligned.m8n8.x4.trans.shared.b16 {%0,%1,%2,%3}, [%4];"
        : "=r"(r0), "=r"(r1), "=r"(r2), "=r"(r3) : "r"(addr));
}
__device__ __forceinline__ void mma_bf16(float* d, const uint32_t* a, const uint32_t* b){
    asm volatile("mma.sync.aligned.m16n8k16.row.col.f32.bf16.bf16.f32 "
        "{%0,%1,%2,%3}, {%4,%5,%6,%7}, {%8,%9}, {%0,%1,%2,%3};"
        : "+f"(d[0]), "+f"(d[1]), "+f"(d[2]), "+f"(d[3])
        : "r"(a[0]), "r"(a[1]), "r"(a[2]), "r"(a[3]), "r"(b[0]), "r"(b[1]));
}
__device__ __forceinline__ uint32_t pack_bf16x2(float lo, float hi){
    __nv_bfloat162 t = __floats2bfloat162_rn(lo, hi);   // .x = lo half
    return *(uint32_t*)&t;
}

// ---------------------------------------------------------------------------
// LayerNorm -> split bf16
// ---------------------------------------------------------------------------
__global__ void ln_kernel(const float* __restrict__ x,
                          const float* __restrict__ gamma,
                          const float* __restrict__ beta) {
    int row = blockIdx.x;
    const float* xr = x + (size_t)row * DIM;
    int t = threadIdx.x;
    float v0 = xr[t], v1 = xr[t+256], v2 = xr[t+512];
    float s  = v0+v1+v2;
    float sq = v0*v0 + v1*v1 + v2*v2;
    __shared__ float red[2][8];
    #pragma unroll
    for (int o=16;o>0;o>>=1){
        s  += __shfl_xor_sync(0xffffffffu, s,  o);
        sq += __shfl_xor_sync(0xffffffffu, sq, o);
    }
    int wid = t>>5, lid = t&31;
    if (lid==0){ red[0][wid]=s; red[1][wid]=sq; }
    __syncthreads();
    if (t==0){
        float ss=0.f, ssq=0.f;
        #pragma unroll
        for (int i=0;i<8;i++){ ss+=red[0][i]; ssq+=red[1][i]; }
        float mu  = ss * (1.0f/DIM);
        float var = ssq * (1.0f/DIM) - mu*mu;
        red[0][0]=mu; red[1][0]=rsqrtf(var + 1e-5f);
    }
    __syncthreads();
    float mu = red[0][0], rstd = red[1][0];
    size_t base = (size_t)row * DIM;
    #pragma unroll
    for (int l=0;l<3;l++){
        int c = t + l*256;
        float in = (l==0)?v0:((l==1)?v1:v2);
        float y = (in-mu)*rstd*gamma[c] + beta[c];
        __nv_bfloat16 h = __float2bfloat16(y);
        g_xn_hi[base+c] = h;
        g_xn_lo[base+c] = __float2bfloat16(y - __bfloat162float(h));
    }
}

// ---------------------------------------------------------------------------
// Weight transpose + split:  g_wt[z][n][k] = split(W_z[k][n])
// ---------------------------------------------------------------------------
__global__ void wconv(const float* __restrict__ Wq, const float* __restrict__ Wk,
                      const float* __restrict__ Wv, const float* __restrict__ Wo) {
    __shared__ float t[32][33];
    int z = blockIdx.z;
    const float* W = (z==0)?Wq : (z==1)?Wk : (z==2)?Wv : Wo;
    __nv_bfloat16* hi = g_wt_hi + (size_t)z*DIM*DIM;
    __nv_bfloat16* lo = g_wt_lo + (size_t)z*DIM*DIM;
    int k0 = blockIdx.y*32, n0 = blockIdx.x*32;
    int tx = threadIdx.x, ty = threadIdx.y;
    t[ty][tx] = W[(size_t)(k0+ty)*DIM + n0+tx];
    __syncthreads();
    float v = t[tx][ty];                 // = W[k0+tx][n0+ty]
    int n = n0+ty, k = k0+tx;
    __nv_bfloat16 h = __float2bfloat16(v);
    hi[(size_t)n*DIM + k] = h;
    lo[(size_t)n*DIM + k] = __float2bfloat16(v - __bfloat162float(h));
}

// ---------------------------------------------------------------------------
// mma.sync bf16 split-GEMM.  CTA tile M=128 x N=64, BK=32, double-buffered
// cp.async. 8 warps (4Mx2N), warp tile 32x32.
// modes 0,1,2 = Q/K/V (A = g_xn, out = split bf16 head layout); 3 = out proj.
// ---------------------------------------------------------------------------
#define BKC     32
#define ASTR    40
#define OFF_AHI 0
#define OFF_ALO (128*ASTR*2)
#define OFF_BHI (OFF_ALO + 128*ASTR*2)
#define OFF_BLO (OFF_BHI + 64*ASTR*2)
#define STAGE   (OFF_BLO + 64*ASTR*2)
#define GEMM_SMEM (2*STAGE)              // 61440

__global__ void __launch_bounds__(256, 1) gemm_mma(
        int base_mode,
        const float* __restrict__ bq, const float* __restrict__ bk,
        const float* __restrict__ bv, const float* __restrict__ bo,
        const float* __restrict__ pos, const float* __restrict__ x,
        float* __restrict__ outp) {
    extern __shared__ char sm[];
    uint32_t sbase = smem_u32(sm);
    int tid = threadIdx.x, wid = tid>>5, lane = tid&31;
    int warp_m = wid>>1, warp_n = wid&1;
    int mode = (base_mode==3) ? 3 : (int)blockIdx.z;
    int col0 = blockIdx.x*64, row0 = blockIdx.y*128;

    const __nv_bfloat16* Bthi = g_wt_hi + (size_t)mode*DIM*DIM;
    const __nv_bfloat16* Btlo = g_wt_lo + (size_t)mode*DIM*DIM;
    const __nv_bfloat16* Ahi  = (mode<3) ? g_xn_hi : g_av_hi;
    const __nv_bfloat16* Alo  = (mode<3) ? g_xn_lo : g_av_lo;

    auto load_chunk = [&](int kt, int s){
        uint32_t sb = sbase + s*STAGE;
        #pragma unroll
        for (int l=0;l<2;l++){
            int i = tid + l*256;
            int r = i>>2, seg = i&3;
            int gk = kt*BKC + seg*8;
            size_t src;
            if (mode < 3) {
                src = (size_t)(row0+r)*DIM + gk;
            } else {
                int rr = row0+r; int bb = rr>>10, tt = rr&1023;
                src = (((size_t)(bb*NH + (gk>>6)))*SEQ + tt)*HD + (gk&63);
            }
            uint32_t dst = sb + OFF_AHI + (uint32_t)(r*(ASTR*2) + seg*16);
            CP_ASYNC16(dst,                         Ahi + src);
            CP_ASYNC16(dst + (OFF_ALO - OFF_AHI),   Alo + src);
        }
        {
            int r = tid>>2, seg = tid&3;
            size_t src = (size_t)(col0+r)*DIM + kt*BKC + seg*8;
            uint32_t dst = sb + OFF_BHI + (uint32_t)(r*(ASTR*2) + seg*16);
            CP_ASYNC16(dst,                         Bthi + src);
            CP_ASYNC16(dst + (OFF_BLO - OFF_BHI),   Btlo + src);
        }
        CP_COMMIT();
    };

    float acc[2][4][4];
    #pragma unroll
    for (int mt=0;mt<2;mt++)
        #pragma unroll
        for (int nt=0;nt<4;nt++)
            #pragma unroll
            for (int e=0;e<4;e++) acc[mt][nt][e]=0.f;

    const int NCHUNK = DIM / BKC;        // 24
    load_chunk(0, 0);

    int quad = lane>>3, r8 = lane&7;
    uint32_t rowA0 = (uint32_t)(warp_m*32 + (quad&1)*8 + r8);
    uint32_t rowB0 = (uint32_t)(warp_n*32 + (quad&1)*8 + r8);
    uint32_t colq  = (uint32_t)((quad>>1)*16);

    for (int kt = 0; kt < NCHUNK; kt++) {
        int s = kt & 1;
        if (kt+1 < NCHUNK) { load_chunk(kt+1, (kt+1)&1); CP_WAIT1(); }
        else               { CP_WAIT0(); }
        __syncthreads();

        uint32_t sb = sbase + s*STAGE;
        #pragma unroll
        for (int k16 = 0; k16 < 2; k16++) {
            uint32_t kb = (uint32_t)(k16*32) + colq;
            uint32_t ah[2][4], al[2][4];
            #pragma unroll
            for (int mt=0;mt<2;mt++){
                uint32_t ad = sb + OFF_AHI + (rowA0 + mt*16)*(ASTR*2) + kb;
                ldm_x4(ah[mt][0],ah[mt][1],ah[mt][2],ah[mt][3], ad);
                ldm_x4(al[mt][0],al[mt][1],al[mt][2],al[mt][3], ad + (OFF_ALO-OFF_AHI));
            }
            #pragma unroll
            for (int half=0; half<2; half++){
                uint32_t bd = sb + OFF_BHI + (rowB0 + half*16)*(ASTR*2) + kb;
                uint32_t h0,h1,h2,h3, l0,l1,l2,l3;
                ldm_x4(h0,h1,h2,h3, bd);
                ldm_x4(l0,l1,l2,l3, bd + (OFF_BLO-OFF_BHI));
                uint32_t bh0[2]={h0,h2}, bh1[2]={h1,h3};
                uint32_t bl0[2]={l0,l2}, bl1[2]={l1,l3};
                #pragma unroll
                for (int mt=0;mt<2;mt++){
                    mma_bf16(acc[mt][half*2+0], ah[mt], bh0);
                    mma_bf16(acc[mt][half*2+1], ah[mt], bh1);
                    mma_bf16(acc[mt][half*2+0], ah[mt], bl0);
                    mma_bf16(acc[mt][half*2+1], ah[mt], bl1);
                    mma_bf16(acc[mt][half*2+0], al[mt], bh0);
                    mma_bf16(acc[mt][half*2+1], al[mt], bh1);
                }
            }
        }
        __syncthreads();
    }

    // ---- epilogue ----
    int rA = lane>>2, cA = (lane&3)*2;
    #pragma unroll
    for (int mt=0;mt<2;mt++){
        #pragma unroll
        for (int nt=0;nt<4;nt++){
            int c = col0 + warp_n*32 + nt*8 + cA;
            #pragma unroll
            for (int half=0; half<2; half++){
                int m = row0 + warp_m*32 + mt*16 + rA + half*8;
                float v0 = acc[mt][nt][half*2+0];
                float v1 = acc[mt][nt][half*2+1];
                if (mode < 3) {
                    const float* bias = (mode==0)?bq : (mode==1)?bk : bv;
                    __nv_bfloat16* oh = (mode==0)?g_qh : (mode==1)?g_kh : g_vh;
                    __nv_bfloat16* ol = (mode==0)?g_ql : (mode==1)?g_kl : g_vl;
                    int bb = m>>10, tt = m&1023, h = c>>6;
                    size_t ob = (((size_t)(bb*NH + h))*SEQ + tt)*HD + (c&63);
                    v0 += bias[c]; v1 += bias[c+1];
                    if (mode == 0) {
                        const float* pr = pos + (size_t)m*DIM + c;
                        v0 = (v0 + pr[0]) * 0.125f;
                        v1 = (v1 + pr[1]) * 0.125f;
                    }
                    __nv_bfloat16 h0 = __float2bfloat16(v0);
                    __nv_bfloat16 h1 = __float2bfloat16(v1);
                    oh[ob+0] = h0; ol[ob+0] = __float2bfloat16(v0 - __bfloat162float(h0));
                    oh[ob+1] = h1; ol[ob+1] = __float2bfloat16(v1 - __bfloat162float(h1));
                } else {
                    size_t rb = (size_t)m*DIM + c;
                    outp[rb+0] = v0 + bo[c]   + x[rb+0];
                    outp[rb+1] = v1 + bo[c+1] + x[rb+1];
                }
            }
        }
    }
}

// ---------------------------------------------------------------------------
// Tensor-core flash attention, 2 CTAs/SM.
// Block: 128 queries x one (b,h); 8 warps x 16 rows. K-tiles of 64 keys,
// double-buffered cp.async. Q is STAGED through buffer 0 (fragments preloaded
// before the mainloop), so smem = 2 KV stage buffers only (73.7 KB).
// __launch_bounds__(256,2) caps regs at 128 for 2 CTAs/SM.
// ---------------------------------------------------------------------------
#define ATR        144                    // bytes per smem row
#define AT_STG_SZ  (4*64*ATR)             // 36864 : KHI,KLO,VHI,VLO
#define AT_BUF0    0
#define AT_BUF1    AT_STG_SZ
#define AT_K_HI    0
#define AT_K_LO    (64*ATR)
#define AT_V_HI    (2*64*ATR)
#define AT_V_LO    (3*64*ATR)
#define ATT_SMEM   (2*AT_STG_SZ)          // 73728

__global__ void __launch_bounds__(256, 2) attn_mma() {
    extern __shared__ char sm[];
    uint32_t sbase = smem_u32(sm);
    int tid = threadIdx.x, wid = tid>>5, lane = tid&31;
    int bh = blockIdx.y;
    int q0 = blockIdx.x * 128;
    int wq0 = wid * 16;

    size_t hbase = (size_t)bh*SEQ*HD;
    const __nv_bfloat16* Qh = g_qh + hbase + (size_t)q0*HD;
    const __nv_bfloat16* Ql = g_ql + hbase + (size_t)q0*HD;

    // ---- group 0: Q (hi at buf0+0, lo at buf0+128*ATR) ----
    #pragma unroll
    for (int l=0;l<8;l++){
        int i = tid + l*256;            // 0..2047
        int mat = i>>10;                // 0=hi 1=lo
        int r = (i&1023)>>3, seg = i&7;
        const __nv_bfloat16* src = (mat? Ql : Qh) + (size_t)r*HD + seg*8;
        uint32_t dst = sbase + AT_BUF0 + (uint32_t)(mat*(128*ATR) + r*ATR + seg*16);
        CP_ASYNC16(dst, src);
    }
    CP_COMMIT();
    // ---- group 1: KV tile 0 into buf1 ----
    #pragma unroll
    for (int l=0;l<8;l++){
        int i = tid + l*256;
        int mat = i>>9;                 // 0..3
        int r = (i&511)>>3, seg = i&7;
        const __nv_bfloat16* base = (mat==0)? g_kh : (mat==1)? g_kl : (mat==2)? g_vh : g_vl;
        const __nv_bfloat16* src = base + hbase + (size_t)r*HD + seg*8;
        uint32_t dst = sbase + AT_BUF1 + (uint32_t)(mat*(64*ATR) + r*ATR + seg*16);
        CP_ASYNC16(dst, src);
    }
    CP_COMMIT();

    int g = lane>>3, r8 = lane&7;

    // ---- wait for Q, preload fragments, release buf0 ----
    CP_WAIT1();
    __syncthreads();
    uint32_t qh[4][4], ql[4][4];
    {
        uint32_t qrow = (uint32_t)(wq0 + ((g&1)?8:0) + r8);
        #pragma unroll
        for (int t=0;t<4;t++){
            uint32_t ad = sbase + AT_BUF0 + qrow*ATR + (uint32_t)(32*t + ((g&2)?16:0));
            ldm_x4(qh[t][0],qh[t][1],qh[t][2],qh[t][3], ad);
            ldm_x4(ql[t][0],ql[t][1],ql[t][2],ql[t][3], ad + 128*ATR);
        }
    }
    __syncthreads();   // all warps done reading buf0 before KV1 overwrites it

    float oacc[8][4];
    #pragma unroll
    for (int f=0;f<8;f++)
        #pragma unroll
        for (int e=0;e<4;e++) oacc[f][e]=0.f;
    float m0 = -1e30f, m1 = -1e30f, l0 = 0.f, l1 = 0.f;

    const int NKT = SEQ/64;    // 16
    for (int kt = 0; kt < NKT; kt++) {
        // tile kt lives in buffer (kt+1)&1 : KV0->buf1, KV1->buf0, ...
        if (kt+1 < NKT) {
            uint32_t sb = sbase + ((kt&1)? AT_BUF1 : AT_BUF0);
            #pragma unroll
            for (int l=0;l<8;l++){
                int i = tid + l*256;
                int mat = i>>9;
                int r = (i&511)>>3, seg = i&7;
                const __nv_bfloat16* base = (mat==0)? g_kh : (mat==1)? g_kl : (mat==2)? g_vh : g_vl;
                const __nv_bfloat16* src = base + hbase + (size_t)((kt+1)*64 + r)*HD + seg*8;
                uint32_t dst = sb + (uint32_t)(mat*(64*ATR) + r*ATR + seg*16);
                CP_ASYNC16(dst, src);
            }
            CP_COMMIT();
            CP_WAIT1();
        } else {
            CP_WAIT0();
        }
        __syncthreads();

        uint32_t stg = sbase + ((kt&1)? AT_BUF0 : AT_BUF1);

        // ---- S = Q K^T (16q x 64 keys per warp), 3-term split ----
        float sv[8][4];
        #pragma unroll
        for (int f=0;f<8;f++)
            #pragma unroll
            for (int e=0;e<4;e++) sv[f][e]=0.f;

        uint32_t krow_off = (uint32_t)(((g&2)?8:0) + r8);
        uint32_t kcol_b   = (uint32_t)((g&1)?16:0);
        #pragma unroll
        for (int j=0;j<4;j++){
            #pragma unroll
            for (int t=0;t<4;t++){
                uint32_t ad = stg + (uint32_t)((16*j)+krow_off)*ATR + (uint32_t)(32*t) + kcol_b;
                uint32_t b0,b1,b2,b3, c0,c1,c2,c3;
                ldm_x4(b0,b1,b2,b3, ad + AT_K_HI);
                ldm_x4(c0,c1,c2,c3, ad + AT_K_LO);
                uint32_t bh0[2]={b0,b1}, bh1[2]={b2,b3};
                uint32_t bl0[2]={c0,c1}, bl1[2]={c2,c3};
                mma_bf16(sv[2*j],   qh[t], bh0);
                mma_bf16(sv[2*j],   qh[t], bl0);
                mma_bf16(sv[2*j],   ql[t], bh0);
                mma_bf16(sv[2*j+1], qh[t], bh1);
                mma_bf16(sv[2*j+1], qh[t], bl1);
                mma_bf16(sv[2*j+1], ql[t], bh1);
            }
        }

        // ---- online softmax in fragments (rows: gID and gID+8) ----
        float mx0 = -1e30f, mx1 = -1e30f;
        #pragma unroll
        for (int f=0;f<8;f++){
            mx0 = fmaxf(mx0, fmaxf(sv[f][0], sv[f][1]));
            mx1 = fmaxf(mx1, fmaxf(sv[f][2], sv[f][3]));
        }
        #pragma unroll
        for (int off=1; off<4; off<<=1){
            mx0 = fmaxf(mx0, __shfl_xor_sync(0xffffffffu, mx0, off));
            mx1 = fmaxf(mx1, __shfl_xor_sync(0xffffffffu, mx1, off));
        }
        float mn0 = fmaxf(m0, mx0), mn1 = fmaxf(m1, mx1);
        float sc0 = __expf(m0 - mn0), sc1 = __expf(m1 - mn1);
        m0 = mn0; m1 = mn1;
        float sum0 = 0.f, sum1 = 0.f;
        #pragma unroll
        for (int f=0;f<8;f++){
            sv[f][0] = __expf(sv[f][0] - m0);
            sv[f][1] = __expf(sv[f][1] - m0);
            sv[f][2] = __expf(sv[f][2] - m1);
            sv[f][3] = __expf(sv[f][3] - m1);
            sum0 += sv[f][0] + sv[f][1];
            sum1 += sv[f][2] + sv[f][3];
        }
        #pragma unroll
        for (int off=1; off<4; off<<=1){
            sum0 += __shfl_xor_sync(0xffffffffu, sum0, off);
            sum1 += __shfl_xor_sync(0xffffffffu, sum1, off);
        }
        l0 = l0*sc0 + sum0;
        l1 = l1*sc1 + sum1;
        #pragma unroll
        for (int f=0;f<8;f++){
            oacc[f][0] *= sc0; oacc[f][1] *= sc0;
            oacc[f][2] *= sc1; oacc[f][3] *= sc1;
        }

        // ---- O += P V, P in registers (C-frag == A-frag), 3-term split ----
        uint32_t vrow_off = (uint32_t)(((g&1)?8:0) + r8);
        uint32_t vcol_b   = (uint32_t)((g&2)?16:0);
        #pragma unroll
        for (int j=0;j<4;j++){
            uint32_t pah[4], pal[4];
            #pragma unroll
            for (int hf=0; hf<2; hf++){
                #pragma unroll
                for (int pp=0; pp<2; pp++){
                    float e0 = sv[2*j+hf][pp*2+0];
                    float e1 = sv[2*j+hf][pp*2+1];
                    __nv_bfloat16 b0 = __float2bfloat16(e0);
                    __nv_bfloat16 b1 = __float2bfloat16(e1);
                    pah[hf*2+pp] = pack_bf16x2(__bfloat162float(b0), __bfloat162float(b1));
                    pal[hf*2+pp] = pack_bf16x2(e0 - __bfloat162float(b0),
                                               e1 - __bfloat162float(b1));
                }
            }
            uint32_t pa_h[4] = {pah[0], pah[1], pah[2], pah[3]};
            uint32_t pa_l[4] = {pal[0], pal[1], pal[2], pal[3]};
            #pragma unroll
            for (int gg=0; gg<4; gg++){
                uint32_t ad = stg + (uint32_t)((16*j)+vrow_off)*ATR + (uint32_t)(32*gg) + vcol_b;
                uint32_t v0,v1,v2,v3, w0,w1,w2,w3;
                ldm_x4_t(v0,v1,v2,v3, ad + AT_V_HI);
                ldm_x4_t(w0,w1,w2,w3, ad + AT_V_LO);
                uint32_t bh0[2]={v0,v1}, bh1[2]={v2,v3};
                uint32_t bl0[2]={w0,w1}, bl1[2]={w2,w3};
                mma_bf16(oacc[2*gg],   pa_h, bh0);
                mma_bf16(oacc[2*gg],   pa_h, bl0);
                mma_bf16(oacc[2*gg],   pa_l, bh0);
                mma_bf16(oacc[2*gg+1], pa_h, bh1);
                mma_bf16(oacc[2*gg+1], pa_h, bl1);
                mma_bf16(oacc[2*gg+1], pa_l, bh1);
            }
        }
        __syncthreads();
    }

    // ---- epilogue: normalize, split, store head-layout ----
    float inv0 = 1.0f / l0, inv1 = 1.0f / l1;
    int gID = lane>>2, c2 = (lane&3)*2;
    size_t ob0 = hbase + (size_t)(q0 + wq0 + gID)*HD;
    size_t ob1 = hbase + (size_t)(q0 + wq0 + gID + 8)*HD;
    #pragma unroll
    for (int f=0;f<8;f++){
        int d = f*8 + c2;
        float a0 = oacc[f][0]*inv0, a1 = oacc[f][1]*inv0;
        float b0 = oacc[f][2]*inv1, b1 = oacc[f][3]*inv1;
        __nv_bfloat16 h;
        h = __float2bfloat16(a0); g_av_hi[ob0+d]   = h; g_av_lo[ob0+d]   = __float2bfloat16(a0 - __bfloat162float(h));
        h = __float2bfloat16(a1); g_av_hi[ob0+d+1] = h; g_av_lo[ob0+d+1] = __float2bfloat16(a1 - __bfloat162float(h));
        h = __float2bfloat16(b0); g_av_hi[ob1+d]   = h; g_av_lo[ob1+d]   = __float2bfloat16(b0 - __bfloat162float(h));
        h = __float2bfloat16(b1); g_av_hi[ob1+d+1] = h; g_av_lo[ob1+d+1] = __float2bfloat16(b1 - __bfloat162float(h));
    }
}

// ---------------------------------------------------------------------------
extern "C" void kernel_launch(void* const* d_in, const int* in_sizes, int n_in,
                              void* d_out, int out_size) {
    const float* x     = (const float*)d_in[0];
    const float* pos   = (const float*)d_in[1];
    const float* gamma = (const float*)d_in[2];
    const float* beta  = (const float*)d_in[3];
    const float* Wq    = (const float*)d_in[4];
    const float* bq    = (const float*)d_in[5];
    const float* Wk    = (const float*)d_in[6];
    const float* bk    = (const float*)d_in[7];
    const float* Wv    = (const float*)d_in[8];
    const float* bv    = (const float*)d_in[9];
    const float* Wo    = (const float*)d_in[10];
    const float* bo    = (const float*)d_in[11];
    float* out = (float*)d_out;

    static bool s_attr_done = false;
    if (!s_attr_done) {
        cudaFuncSetAttribute(gemm_mma, cudaFuncAttributeMaxDynamicSharedMemorySize,
                             GEMM_SMEM);
        cudaFuncSetAttribute(attn_mma, cudaFuncAttributeMaxDynamicSharedMemorySize,
                             ATT_SMEM);
        s_attr_done = true;
    }

    ln_kernel<<<ROWS, 256>>>(x, gamma, beta);
    wconv<<<dim3(24, 24, 4), dim3(32, 32)>>>(Wq, Wk, Wv, Wo);

    gemm_mma<<<dim3(12, 64, 3), 256, GEMM_SMEM>>>(0, bq, bk, bv, bo, pos, x, out);

    attn_mma<<<dim3(SEQ/128, BATCH*NH), 256, ATT_SMEM>>>();

    gemm_mma<<<dim3(12, 64, 1), 256, GEMM_SMEM>>>(3, bq, bk, bv, bo, pos, x, out);
}